// round 2
// baseline (speedup 1.0000x reference)
#include <cuda_runtime.h>
#include <cstdint>
#include <math.h>

// Problem constants
// x: (8, 4096, 512) f32 ; w_qkv: (1536, 512) ; w_proj: (512, 512) ; b_proj: (512)
// H=8 heads, head_dim=64, W=64 window, SHIFT=32, SCALE=0.125
#define NTOK (8 * 4096)

// Scratch (allocation-free rule: __device__ globals)
__device__ float g_qkv[(size_t)NTOK * 1536]; // (tok, 1536) : [q(8x64) | k(8x64) | v(8x64)]
__device__ float g_att[(size_t)NTOK * 512];  // scrambled attention output, pre-proj

// ----------------------------------------------------------------------------
// SGEMM: C[m,n] = sum_k A[m,k] * W[n,k]   (A: Mx512 row-major, W: Nx512 row-major)
// MODE 0: QKV  — A = x with roll(-32) on row index, C = g_qkv (LDC=1536), no bias
// MODE 1: PROJ — A = g_att,                        C = d_out with roll(+32) rows,
//                LDC=512, + bias
// Tile: BM=BN=128, BK=8, 256 threads, 8x8 per thread.
// ----------------------------------------------------------------------------
template <int MODE>
__global__ __launch_bounds__(256, 2) void sgemm_kernel(const float* __restrict__ Ain,
                                                       const float* __restrict__ Wmat,
                                                       const float* __restrict__ bias,
                                                       float* __restrict__ Cout)
{
    constexpr int LDC = (MODE == 0) ? 1536 : 512;

    __shared__ float As[8][128];
    __shared__ float Bs[8][128];

    const float* A = (MODE == 0) ? Ain : g_att;

    const int tid = threadIdx.x;
    const int m0 = blockIdx.y * 128;
    const int n0 = blockIdx.x * 128;

    // global-load mapping: 2 threads per tile row, float4 along K
    const int lrow = tid >> 1;
    const int lcol = (tid & 1) * 4;

    int arow = m0 + lrow;
    if (MODE == 0) {
        // roll(x, -32, axis=seq): rolled row n reads source row (n+32)%4096
        arow = (arow & ~4095) | (((arow & 4095) + 32) & 4095);
    }
    const float* aptr = A + (size_t)arow * 512 + lcol;
    const float* wptr = Wmat + (size_t)(n0 + lrow) * 512 + lcol;

    const int tx = tid & 15;
    const int ty = tid >> 4;

    float acc[8][8];
#pragma unroll
    for (int i = 0; i < 8; i++)
#pragma unroll
        for (int j = 0; j < 8; j++) acc[i][j] = 0.f;

    for (int k0 = 0; k0 < 512; k0 += 8) {
        float4 av = *(const float4*)(aptr + k0);
        float4 bv = *(const float4*)(wptr + k0);
        As[lcol + 0][lrow] = av.x;
        As[lcol + 1][lrow] = av.y;
        As[lcol + 2][lrow] = av.z;
        As[lcol + 3][lrow] = av.w;
        Bs[lcol + 0][lrow] = bv.x;
        Bs[lcol + 1][lrow] = bv.y;
        Bs[lcol + 2][lrow] = bv.z;
        Bs[lcol + 3][lrow] = bv.w;
        __syncthreads();

#pragma unroll
        for (int k = 0; k < 8; k++) {
            float a[8], b[8];
            *(float4*)&a[0] = *(const float4*)&As[k][ty * 8];
            *(float4*)&a[4] = *(const float4*)&As[k][ty * 8 + 4];
            *(float4*)&b[0] = *(const float4*)&Bs[k][tx * 8];
            *(float4*)&b[4] = *(const float4*)&Bs[k][tx * 8 + 4];
#pragma unroll
            for (int i = 0; i < 8; i++)
#pragma unroll
                for (int j = 0; j < 8; j++) acc[i][j] += a[i] * b[j];
        }
        __syncthreads();
    }

    float bb[8];
    if (MODE == 1) {
#pragma unroll
        for (int j = 0; j < 8; j++) bb[j] = bias[n0 + tx * 8 + j];
    }

#pragma unroll
    for (int i = 0; i < 8; i++) {
        int m = m0 + ty * 8 + i;
        int mo = m;
        if (MODE == 1) {
            // roll(out, +32): row n2 of y lands at output row (n2+32)%4096
            mo = (m & ~4095) | (((m & 4095) + 32) & 4095);
        }
        float* cp;
        if (MODE == 0)
            cp = g_qkv + (size_t)mo * LDC + n0 + tx * 8;
        else
            cp = Cout + (size_t)mo * LDC + n0 + tx * 8;

        float4 v0, v1;
        v0.x = acc[i][0]; v0.y = acc[i][1]; v0.z = acc[i][2]; v0.w = acc[i][3];
        v1.x = acc[i][4]; v1.y = acc[i][5]; v1.z = acc[i][6]; v1.w = acc[i][7];
        if (MODE == 1) {
            v0.x += bb[0]; v0.y += bb[1]; v0.z += bb[2]; v0.w += bb[3];
            v1.x += bb[4]; v1.y += bb[5]; v1.z += bb[6]; v1.w += bb[7];
        }
        *(float4*)(cp + 0) = v0;
        *(float4*)(cp + 4) = v1;
    }
}

// ----------------------------------------------------------------------------
// Per-token 8x8 head-mixing attention + output scramble.
// Token tok = b*4096 + n, n = wi*64 + w.
//   S[h,g] = 0.125 * sum_d q[h,d] k[g,d];  P = softmax_g(S)
//   o[h,d] = sum_g P[h,g] v[g,d]
//   g_att[b, wi*64 + h*8 + w/8, (w%8)*64 + d] = o[h,d]
// Block = 64 threads = 8 tokens x 8 heads. k,v staged in smem (pad 8 floats).
// ----------------------------------------------------------------------------
__global__ __launch_bounds__(64) void attn_kernel()
{
    __shared__ float kv[8][1032]; // [token][ k(512) | v(512) ], stride 1032 kills bank conflicts

    const int tid = threadIdx.x;
    const int tok0 = blockIdx.x * 8;

    // cooperative load of k,v (1024 floats / token) as float4, coalesced
    for (int i = tid; i < 8 * 256; i += 64) {
        int t = i >> 8;
        int off = i & 255;
        float4 val = *(const float4*)(g_qkv + (size_t)(tok0 + t) * 1536 + 512 + off * 4);
        *(float4*)(&kv[t][off * 4]) = val;
    }
    __syncthreads();

    const int lt = tid >> 3;  // local token 0..7
    const int h = tid & 7;    // head
    const int tok = tok0 + lt;

    const float* qp = g_qkv + (size_t)tok * 1536 + h * 64;

    float S[8];
#pragma unroll
    for (int g = 0; g < 8; g++) S[g] = 0.f;

#pragma unroll
    for (int d0 = 0; d0 < 64; d0 += 4) {
        float4 q4 = *(const float4*)(qp + d0);
#pragma unroll
        for (int g = 0; g < 8; g++) {
            const float* kr = &kv[lt][g * 64 + d0];
            S[g] += q4.x * kr[0] + q4.y * kr[1] + q4.z * kr[2] + q4.w * kr[3];
        }
    }

    // scale + softmax over g
    float mx = -INFINITY;
#pragma unroll
    for (int g = 0; g < 8; g++) {
        S[g] *= 0.125f; // (512/8)^-0.5
        mx = fmaxf(mx, S[g]);
    }
    float sum = 0.f;
#pragma unroll
    for (int g = 0; g < 8; g++) {
        S[g] = expf(S[g] - mx);
        sum += S[g];
    }
    float inv = 1.f / sum;
#pragma unroll
    for (int g = 0; g < 8; g++) S[g] *= inv;

    // o = P @ v, write with the transpose/reshape scramble applied
    const int n = tok & 4095;
    const int wi = n >> 6;
    const int w = n & 63;
    const int n2 = (wi << 6) | (h << 3) | (w >> 3);
    float* op = g_att + (size_t)((tok & ~4095) | n2) * 512 + ((w & 7) << 6);

#pragma unroll
    for (int d0 = 0; d0 < 64; d0 += 4) {
        float4 o4 = {0.f, 0.f, 0.f, 0.f};
#pragma unroll
        for (int g = 0; g < 8; g++) {
            const float* vr = &kv[lt][512 + g * 64 + d0];
            o4.x += S[g] * vr[0];
            o4.y += S[g] * vr[1];
            o4.z += S[g] * vr[2];
            o4.w += S[g] * vr[3];
        }
        *(float4*)(op + d0) = o4;
    }
}

extern "C" void kernel_launch(void* const* d_in, const int* in_sizes, int n_in,
                              void* d_out, int out_size)
{
    const float* x = (const float*)d_in[0];      // (8,4096,512)
    const float* w_qkv = (const float*)d_in[1];  // (1536,512)
    const float* w_proj = (const float*)d_in[2]; // (512,512)
    const float* b_proj = (const float*)d_in[3]; // (512,)
    float* out = (float*)d_out;                  // (8,4096,512)

    (void)in_sizes; (void)n_in; (void)out_size;

    // 1) QKV GEMM with fused roll(-32) on input rows -> g_qkv
    sgemm_kernel<0><<<dim3(1536 / 128, NTOK / 128), 256>>>(x, w_qkv, nullptr, nullptr);

    // 2) per-token 8x8 head attention + scramble -> g_att
    attn_kernel<<<NTOK / 8, 64>>>();

    // 3) proj GEMM + bias with fused roll(+32) on output rows -> d_out
    sgemm_kernel<1><<<dim3(512 / 128, NTOK / 128), 256>>>(nullptr, w_proj, b_proj, out);
}

// round 4
// speedup vs baseline: 4.6350x; 4.6350x over previous
#include <cuda_runtime.h>
#include <cuda_fp16.h>
#include <mma.h>
#include <cstdint>
#include <math.h>

using namespace nvcuda;

// x: (8,4096,512) f32 ; w_qkv: (1536,512) ; w_proj: (512,512) ; b_proj: (512)
// H=8, head_dim=64, W=64, SHIFT=32, SCALE=0.125
#define NTOK (8 * 4096)

// -------- scratch (__device__ globals; no allocation allowed) --------
__device__ __half g_x16[(size_t)NTOK * 512];    // rolled(-32) x, fp16
__device__ float  g_qkv[(size_t)NTOK * 1536];   // q|k|v per token, fp32
__device__ __half g_att16[(size_t)NTOK * 512];  // scrambled attention out, fp16
__device__ __half g_wqkv16[1536 * 512];
__device__ __half g_wproj16[512 * 512];

// ---------------------------------------------------------------------------
// conversion kernels (fp32 -> fp16), roll(-32) fused into x conversion
// ---------------------------------------------------------------------------
__global__ void conv_x_kernel(const float* __restrict__ x) {
    size_t idx = (size_t)blockIdx.x * 256 + threadIdx.x; // one float4 each
    int m = (int)(idx >> 7);
    int c = (int)(idx & 127) * 4;
    int msrc = (m & ~4095) | (((m & 4095) + 32) & 4095); // roll(-32)
    float4 v = *(const float4*)(x + (size_t)msrc * 512 + c);
    __half2 h0 = __floats2half2_rn(v.x, v.y);
    __half2 h1 = __floats2half2_rn(v.z, v.w);
    uint2 u;
    u.x = *(const unsigned*)&h0;
    u.y = *(const unsigned*)&h1;
    *(uint2*)(g_x16 + (size_t)m * 512 + c) = u;
}

__global__ void conv_w_kernel(const float* __restrict__ src, __half* __restrict__ dst, int n4) {
    int idx = blockIdx.x * 256 + threadIdx.x;
    if (idx >= n4) return;
    float4 v = *(const float4*)(src + (size_t)idx * 4);
    __half2 h0 = __floats2half2_rn(v.x, v.y);
    __half2 h1 = __floats2half2_rn(v.z, v.w);
    uint2 u;
    u.x = *(const unsigned*)&h0;
    u.y = *(const unsigned*)&h1;
    *(uint2*)(dst + (size_t)idx * 4) = u;
}

// ---------------------------------------------------------------------------
// Tensor-core GEMM via wmma: C[m,n] = sum_k A[m,k] * B[n,k], K = 512.
// A: Mx512 fp16 row-major. B: Nx512 fp16 row-major (= col-major matrix_b).
// MODE 0: A=g_x16,  B=g_wqkv16,  C=g_qkv (fp32, ldc 1536), no bias
// MODE 1: A=g_att16, B=g_wproj16, C=d_out (ldc 512), + bias, + roll(+32) rows
// BM=BN=128, BK=64, 256 thr = 8 warps (4 along M x 2 along N), warp tile 32x64.
// ---------------------------------------------------------------------------
template <int MODE>
__global__ __launch_bounds__(256) void gemm_wmma(const __half* __restrict__ Aglob,
                                                 const __half* __restrict__ Bglob,
                                                 const float* __restrict__ bias,
                                                 float* __restrict__ Cout)
{
    constexpr int BK = 64;
    constexpr int LDS = BK + 8; // 72, multiple of 8, de-conflicted
    __shared__ __half sA[128][LDS];
    __shared__ __half sB[128][LDS];
    __shared__ float sBias[16][136]; // MODE 1: row-broadcast bias staging

    const int tid = threadIdx.x;
    const int wid = tid >> 5;
    const int warpM = wid & 3;  // 0..3 -> 32-row slab
    const int warpN = wid >> 2; // 0..1 -> 64-col slab
    const int m0 = blockIdx.y * 128;
    const int n0 = blockIdx.x * 128;

    wmma::fragment<wmma::accumulator, 16, 16, 16, float> acc[2][4];

    if (MODE == 1) {
        if (tid < 128) {
            float bv = bias[n0 + tid];
#pragma unroll
            for (int r = 0; r < 16; ++r) sBias[r][tid] = bv;
        }
        __syncthreads();
#pragma unroll
        for (int i = 0; i < 2; ++i)
#pragma unroll
            for (int j = 0; j < 4; ++j)
                wmma::load_matrix_sync(acc[i][j], &sBias[0][warpN * 64 + j * 16], 136,
                                       wmma::mem_row_major);
        __syncthreads();
    } else {
#pragma unroll
        for (int i = 0; i < 2; ++i)
#pragma unroll
            for (int j = 0; j < 4; ++j) wmma::fill_fragment(acc[i][j], 0.0f);
    }

    // global-load mapping: 8 threads per row (8x uint4 = 64 fp16), 32 rows/pass
    const int lr = tid >> 3;      // 0..31
    const int lc = (tid & 7) * 8; // fp16 col offset

    for (int kt = 0; kt < 512; kt += BK) {
#pragma unroll
        for (int p = 0; p < 4; ++p) {
            int row = p * 32 + lr;
            *(uint4*)(&sA[row][lc]) =
                *(const uint4*)(Aglob + (size_t)(m0 + row) * 512 + kt + lc);
            *(uint4*)(&sB[row][lc]) =
                *(const uint4*)(Bglob + (size_t)(n0 + row) * 512 + kt + lc);
        }
        __syncthreads();

#pragma unroll
        for (int ks = 0; ks < BK; ks += 16) {
            wmma::fragment<wmma::matrix_a, 16, 16, 16, __half, wmma::row_major> af[2];
#pragma unroll
            for (int i = 0; i < 2; ++i)
                wmma::load_matrix_sync(af[i], &sA[warpM * 32 + i * 16][ks], LDS);
#pragma unroll
            for (int j = 0; j < 4; ++j) {
                wmma::fragment<wmma::matrix_b, 16, 16, 16, __half, wmma::col_major> bf;
                wmma::load_matrix_sync(bf, &sB[warpN * 64 + j * 16][ks], LDS);
#pragma unroll
                for (int i = 0; i < 2; ++i)
                    wmma::mma_sync(acc[i][j], af[i], bf, acc[i][j]);
            }
        }
        __syncthreads();
    }

    // epilogue: direct global stores (16-row fragments stay contiguous under roll)
#pragma unroll
    for (int i = 0; i < 2; ++i) {
        int m = m0 + warpM * 32 + i * 16;
        if (MODE == 0) {
            float* cp = g_qkv + (size_t)m * 1536 + n0 + warpN * 64;
#pragma unroll
            for (int j = 0; j < 4; ++j)
                wmma::store_matrix_sync(cp + j * 16, acc[i][j], 1536, wmma::mem_row_major);
        } else {
            int r = (m & 4095) + 32;
            if (r >= 4096) r -= 4096;
            int mo = (m & ~4095) | r; // roll(+32); 16-row frag stays contiguous
            float* cp = Cout + (size_t)mo * 512 + n0 + warpN * 64;
#pragma unroll
            for (int j = 0; j < 4; ++j)
                wmma::store_matrix_sync(cp + j * 16, acc[i][j], 512, wmma::mem_row_major);
        }
    }
}

// ---------------------------------------------------------------------------
// Per-token 8x8 head-mixing attention + output scramble (fp32 math, fp16 out)
// Token tok = b*4096 + n, n = wi*64 + w:
//   S[h,g] = 0.125 * q[h]·k[g];  P = softmax_g(S);  o[h] = P·v
//   g_att16[b, wi*64 + h*8 + w/8, (w%8)*64 + d] = o[h,d]
// ---------------------------------------------------------------------------
__global__ __launch_bounds__(64) void attn_kernel()
{
    __shared__ float kv[8][1032]; // [token][ k(512) | v(512) ]

    const int tid = threadIdx.x;
    const int tok0 = blockIdx.x * 8;

    for (int i = tid; i < 8 * 256; i += 64) {
        int t = i >> 8;
        int off = i & 255;
        float4 val = *(const float4*)(g_qkv + (size_t)(tok0 + t) * 1536 + 512 + off * 4);
        *(float4*)(&kv[t][off * 4]) = val;
    }
    __syncthreads();

    const int lt = tid >> 3;
    const int h = tid & 7;
    const int tok = tok0 + lt;

    const float* qp = g_qkv + (size_t)tok * 1536 + h * 64;

    float S[8];
#pragma unroll
    for (int g = 0; g < 8; g++) S[g] = 0.f;

#pragma unroll
    for (int d0 = 0; d0 < 64; d0 += 4) {
        float4 q4 = *(const float4*)(qp + d0);
#pragma unroll
        for (int g = 0; g < 8; g++) {
            const float* kr = &kv[lt][g * 64 + d0];
            S[g] += q4.x * kr[0] + q4.y * kr[1] + q4.z * kr[2] + q4.w * kr[3];
        }
    }

    float mx = -INFINITY;
#pragma unroll
    for (int g = 0; g < 8; g++) {
        S[g] *= 0.125f;
        mx = fmaxf(mx, S[g]);
    }
    float sum = 0.f;
#pragma unroll
    for (int g = 0; g < 8; g++) {
        S[g] = expf(S[g] - mx);
        sum += S[g];
    }
    float inv = 1.f / sum;
#pragma unroll
    for (int g = 0; g < 8; g++) S[g] *= inv;

    const int n = tok & 4095;
    const int wi = n >> 6;
    const int w = n & 63;
    const int n2 = (wi << 6) | (h << 3) | (w >> 3);
    __half* op = g_att16 + (size_t)((tok & ~4095) | n2) * 512 + ((w & 7) << 6);

#pragma unroll
    for (int d0 = 0; d0 < 64; d0 += 4) {
        float4 o4 = {0.f, 0.f, 0.f, 0.f};
#pragma unroll
        for (int g = 0; g < 8; g++) {
            const float* vr = &kv[lt][512 + g * 64 + d0];
            o4.x += S[g] * vr[0];
            o4.y += S[g] * vr[1];
            o4.z += S[g] * vr[2];
            o4.w += S[g] * vr[3];
        }
        __half2 h0 = __floats2half2_rn(o4.x, o4.y);
        __half2 h1 = __floats2half2_rn(o4.z, o4.w);
        uint2 u;
        u.x = *(const unsigned*)&h0;
        u.y = *(const unsigned*)&h1;
        *(uint2*)(op + d0) = u;
    }
}

// ---------------------------------------------------------------------------
extern "C" void kernel_launch(void* const* d_in, const int* in_sizes, int n_in,
                              void* d_out, int out_size)
{
    const float* x = (const float*)d_in[0];
    const float* w_qkv = (const float*)d_in[1];
    const float* w_proj = (const float*)d_in[2];
    const float* b_proj = (const float*)d_in[3];
    float* out = (float*)d_out;
    (void)in_sizes; (void)n_in; (void)out_size;

    __half* wq16;
    __half* wp16;
    __half* x16;
    __half* a16;
    cudaGetSymbolAddress((void**)&wq16, g_wqkv16);
    cudaGetSymbolAddress((void**)&wp16, g_wproj16);
    cudaGetSymbolAddress((void**)&x16, g_x16);
    cudaGetSymbolAddress((void**)&a16, g_att16);

    // 1) fp16 conversions (roll(-32) fused into x)
    conv_x_kernel<<<(NTOK * 512 / 4) / 256, 256>>>(x);
    conv_w_kernel<<<(1536 * 512 / 4 + 255) / 256, 256>>>(w_qkv, wq16, 1536 * 512 / 4);
    conv_w_kernel<<<(512 * 512 / 4 + 255) / 256, 256>>>(w_proj, wp16, 512 * 512 / 4);

    // 2) QKV GEMM (tensor cores) -> g_qkv fp32
    gemm_wmma<0><<<dim3(1536 / 128, NTOK / 128), 256>>>(x16, wq16, nullptr, nullptr);

    // 3) per-token 8x8 head attention + scramble -> g_att16
    attn_kernel<<<NTOK / 8, 64>>>();

    // 4) proj GEMM + bias + roll(+32) -> d_out
    gemm_wmma<1><<<dim3(512 / 128, NTOK / 128), 256>>>(a16, wp16, b_proj, out);
}

// round 5
// speedup vs baseline: 4.8716x; 1.0511x over previous
#include <cuda_runtime.h>
#include <cuda_fp16.h>
#include <mma.h>
#include <cstdint>
#include <math.h>

using namespace nvcuda;

// x: (8,4096,512) f32 ; w_qkv: (1536,512) ; w_proj: (512,512) ; b_proj: (512)
// H=8, head_dim=64, W=64, SHIFT=32, SCALE=0.125
#define NTOK (8 * 4096)

// -------- scratch (__device__ globals; no allocation allowed) --------
__device__ __half g_x16[(size_t)NTOK * 512];     // rolled(-32) x, fp16
__device__ __half g_qkv16[(size_t)NTOK * 1536];  // q|k|v per token, fp16
__device__ __half g_att16[(size_t)NTOK * 512];   // scrambled attention out, fp16
__device__ __half g_wqkv16[1536 * 512];
__device__ __half g_wproj16[512 * 512];

// ---------------------------------------------------------------------------
// cp.async helpers (sm_80+ PTX, valid for compute_103)
// ---------------------------------------------------------------------------
__device__ __forceinline__ void cp_async16(void* smem_dst, const void* gmem_src) {
    unsigned sa = (unsigned)__cvta_generic_to_shared(smem_dst);
    asm volatile("cp.async.cg.shared.global [%0], [%1], 16;" :: "r"(sa), "l"(gmem_src));
}
__device__ __forceinline__ void cp_async_commit() {
    asm volatile("cp.async.commit_group;");
}
__device__ __forceinline__ void cp_async_wait1() {
    asm volatile("cp.async.wait_group 1;");
}

// ---------------------------------------------------------------------------
// conversion kernels (fp32 -> fp16), roll(-32) fused into x conversion
// ---------------------------------------------------------------------------
__global__ void conv_x_kernel(const float* __restrict__ x) {
    size_t idx = (size_t)blockIdx.x * 256 + threadIdx.x; // one float4 each
    int m = (int)(idx >> 7);
    int c = (int)(idx & 127) * 4;
    int msrc = (m & ~4095) | (((m & 4095) + 32) & 4095); // roll(-32)
    float4 v = *(const float4*)(x + (size_t)msrc * 512 + c);
    __half2 h0 = __floats2half2_rn(v.x, v.y);
    __half2 h1 = __floats2half2_rn(v.z, v.w);
    uint2 u;
    u.x = *(const unsigned*)&h0;
    u.y = *(const unsigned*)&h1;
    *(uint2*)(g_x16 + (size_t)m * 512 + c) = u;
}

__global__ void conv_w_kernel(const float* __restrict__ src, __half* __restrict__ dst, int n4) {
    int idx = blockIdx.x * 256 + threadIdx.x;
    if (idx >= n4) return;
    float4 v = *(const float4*)(src + (size_t)idx * 4);
    __half2 h0 = __floats2half2_rn(v.x, v.y);
    __half2 h1 = __floats2half2_rn(v.z, v.w);
    uint2 u;
    u.x = *(const unsigned*)&h0;
    u.y = *(const unsigned*)&h1;
    *(uint2*)(dst + (size_t)idx * 4) = u;
}

// ---------------------------------------------------------------------------
// Tensor-core GEMM, cp.async double-buffered: C[m,n] = sum_k A[m,k]*B[n,k], K=512
// A: Mx512 fp16 row-major. B: Nx512 fp16 row-major (= col-major matrix_b).
// MODE 0: A=g_x16,  B=g_wqkv16,  C=g_qkv16 (fp16, ldc 1536), no bias
// MODE 1: A=g_att16, B=g_wproj16, C=d_out fp32 (ldc 512), + bias, + roll(+32)
// BM=BN=128, BK=32, 2 stages, 256 thr = 8 warps (4 M x 2 N), warp tile 32x64.
// ---------------------------------------------------------------------------
template <int MODE>
__global__ __launch_bounds__(256) void gemm_wmma(const __half* __restrict__ Aglob,
                                                 const __half* __restrict__ Bglob,
                                                 const float* __restrict__ bias,
                                                 float* __restrict__ Cout)
{
    constexpr int BK = 32;
    constexpr int LDS = BK + 8; // 40 halves
    // one raw buffer, unioned between: pipeline tiles / bias staging / epilogue staging
    __shared__ alignas(16) uint8_t smem_raw[2 * 2 * 128 * LDS * 2]; // 40960 B

    auto sA = [&](int s, int r, int c) -> __half* {
        return (__half*)smem_raw + ((size_t)s * 128 * LDS) + r * LDS + c;
    };
    auto sB = [&](int s, int r, int c) -> __half* {
        return (__half*)(smem_raw + 2 * 128 * LDS * 2) + ((size_t)s * 128 * LDS) + r * LDS + c;
    };

    const int tid = threadIdx.x;
    const int wid = tid >> 5;
    const int lane = tid & 31;
    const int warpM = wid & 3;  // 32-row slab
    const int warpN = wid >> 2; // 64-col slab
    const int m0 = blockIdx.y * 128;
    const int n0 = blockIdx.x * 128;

    wmma::fragment<wmma::accumulator, 16, 16, 16, float> acc[2][4];

    if (MODE == 1) {
        // stage row-broadcast bias, load into accumulators (layout-agnostic)
        float (*sBias)[136] = (float (*)[136])smem_raw;
        if (tid < 128) {
            float bv = bias[n0 + tid];
#pragma unroll
            for (int r = 0; r < 16; ++r) sBias[r][tid] = bv;
        }
        __syncthreads();
#pragma unroll
        for (int i = 0; i < 2; ++i)
#pragma unroll
            for (int j = 0; j < 4; ++j)
                wmma::load_matrix_sync(acc[i][j], &sBias[0][warpN * 64 + j * 16], 136,
                                       wmma::mem_row_major);
        __syncthreads();
    } else {
#pragma unroll
        for (int i = 0; i < 2; ++i)
#pragma unroll
            for (int j = 0; j < 4; ++j) wmma::fill_fragment(acc[i][j], 0.0f);
    }

    // cp.async load mapping: 4 threads per row (1 uint4 = 8 halves each),
    // 64 rows per pass, 2 passes -> 128 rows. Per thread: 2xA + 2xB copies.
    const int lr = tid >> 2;       // 0..63
    const int lc = (tid & 3) * 8;  // half col offset in BK

    auto load_stage = [&](int s, int kt) {
        const int k0 = kt * BK;
#pragma unroll
        for (int p = 0; p < 2; ++p) {
            int row = p * 64 + lr;
            cp_async16(sA(s, row, lc), Aglob + (size_t)(m0 + row) * 512 + k0 + lc);
            cp_async16(sB(s, row, lc), Bglob + (size_t)(n0 + row) * 512 + k0 + lc);
        }
    };

    // prologue
    load_stage(0, 0);
    cp_async_commit();

    for (int kt = 0; kt < 16; ++kt) {
        if (kt + 1 < 16) load_stage((kt + 1) & 1, kt + 1);
        cp_async_commit();
        cp_async_wait1();
        __syncthreads();

        const int s = kt & 1;
#pragma unroll
        for (int ks = 0; ks < BK; ks += 16) {
            wmma::fragment<wmma::matrix_a, 16, 16, 16, __half, wmma::row_major> af[2];
#pragma unroll
            for (int i = 0; i < 2; ++i)
                wmma::load_matrix_sync(af[i], sA(s, warpM * 32 + i * 16, ks), LDS);
#pragma unroll
            for (int j = 0; j < 4; ++j) {
                wmma::fragment<wmma::matrix_b, 16, 16, 16, __half, wmma::col_major> bf;
                wmma::load_matrix_sync(bf, sB(s, warpN * 64 + j * 16, ks), LDS);
#pragma unroll
                for (int i = 0; i < 2; ++i)
                    wmma::mma_sync(acc[i][j], af[i], bf, acc[i][j]);
            }
        }
        __syncthreads();
    }

    if (MODE == 0) {
        // fp16 epilogue: stage fp32 frags in smem (per-warp 32x64 patch), convert
        float* stg = (float*)smem_raw + (size_t)(wid & 3) * 2048;
        const int rrow = lane >> 3;      // 0..3
        const int ccol = (lane & 7) * 8; // 0..56
#pragma unroll
        for (int round = 0; round < 2; ++round) {
            if ((wid >> 2) == round) {
#pragma unroll
                for (int i = 0; i < 2; ++i)
#pragma unroll
                    for (int j = 0; j < 4; ++j)
                        wmma::store_matrix_sync(stg + i * 1024 + j * 16, acc[i][j], 64,
                                                wmma::mem_row_major);
                __syncwarp();
#pragma unroll
                for (int rr = 0; rr < 8; ++rr) {
                    int row = rr * 4 + rrow;
                    const float* sp = stg + row * 64 + ccol;
                    __half* gp = g_qkv16 + (size_t)(m0 + warpM * 32 + row) * 1536 +
                                 n0 + warpN * 64 + ccol;
                    float4 a = *(const float4*)(sp);
                    float4 b = *(const float4*)(sp + 4);
                    __half2 h0 = __floats2half2_rn(a.x, a.y);
                    __half2 h1 = __floats2half2_rn(a.z, a.w);
                    __half2 h2 = __floats2half2_rn(b.x, b.y);
                    __half2 h3 = __floats2half2_rn(b.z, b.w);
                    uint4 u;
                    u.x = *(unsigned*)&h0;
                    u.y = *(unsigned*)&h1;
                    u.z = *(unsigned*)&h2;
                    u.w = *(unsigned*)&h3;
                    *(uint4*)gp = u;
                }
            }
            __syncthreads();
        }
    } else {
        // fp32 direct store with roll(+32) (16-row frags stay contiguous)
#pragma unroll
        for (int i = 0; i < 2; ++i) {
            int m = m0 + warpM * 32 + i * 16;
            int r = (m & 4095) + 32;
            if (r >= 4096) r -= 4096;
            int mo = (m & ~4095) | r;
            float* cp = Cout + (size_t)mo * 512 + n0 + warpN * 64;
#pragma unroll
            for (int j = 0; j < 4; ++j)
                wmma::store_matrix_sync(cp + j * 16, acc[i][j], 512, wmma::mem_row_major);
        }
    }
}

// ---------------------------------------------------------------------------
// Per-token 8x8 head-mixing attention + output scramble (fp32 math).
// Reads fp16 qkv, writes fp16 scrambled output.
//   S[h,g] = 0.125 * q[h]·k[g];  P = softmax_g(S);  o[h] = P·v
//   g_att16[b, wi*64 + h*8 + w/8, (w%8)*64 + d] = o[h,d]
// ---------------------------------------------------------------------------
__global__ __launch_bounds__(64) void attn_kernel()
{
    __shared__ float kv[8][1032]; // [token][ k(512) | v(512) ] fp32

    const int tid = threadIdx.x;
    const int tok0 = blockIdx.x * 8;

    // k,v: 1024 halves/token = 128 uint4; 8 tokens = 1024 uint4; 64 thr x 16 it
    for (int i = tid; i < 8 * 128; i += 64) {
        int t = i >> 7;
        int off = i & 127;
        uint4 u = *(const uint4*)(g_qkv16 + (size_t)(tok0 + t) * 1536 + 512 + off * 8);
        const __half2* hp = (const __half2*)&u;
        float* dst = &kv[t][off * 8];
#pragma unroll
        for (int j = 0; j < 4; ++j) {
            float2 f = __half22float2(hp[j]);
            dst[j * 2 + 0] = f.x;
            dst[j * 2 + 1] = f.y;
        }
    }
    __syncthreads();

    const int lt = tid >> 3;
    const int h = tid & 7;
    const int tok = tok0 + lt;

    const __half* qp = g_qkv16 + (size_t)tok * 1536 + h * 64;

    float S[8];
#pragma unroll
    for (int g = 0; g < 8; g++) S[g] = 0.f;

#pragma unroll
    for (int d0 = 0; d0 < 64; d0 += 8) {
        uint4 u = *(const uint4*)(qp + d0);
        const __half2* hp = (const __half2*)&u;
        float qf[8];
#pragma unroll
        for (int j = 0; j < 4; ++j) {
            float2 f = __half22float2(hp[j]);
            qf[j * 2 + 0] = f.x;
            qf[j * 2 + 1] = f.y;
        }
#pragma unroll
        for (int g = 0; g < 8; g++) {
            const float* kr = &kv[lt][g * 64 + d0];
            float s = 0.f;
#pragma unroll
            for (int j = 0; j < 8; ++j) s += qf[j] * kr[j];
            S[g] += s;
        }
    }

    float mx = -INFINITY;
#pragma unroll
    for (int g = 0; g < 8; g++) {
        S[g] *= 0.125f;
        mx = fmaxf(mx, S[g]);
    }
    float sum = 0.f;
#pragma unroll
    for (int g = 0; g < 8; g++) {
        S[g] = expf(S[g] - mx);
        sum += S[g];
    }
    float inv = 1.f / sum;
#pragma unroll
    for (int g = 0; g < 8; g++) S[g] *= inv;

    const int n = tok & 4095;
    const int wi = n >> 6;
    const int w = n & 63;
    const int n2 = (wi << 6) | (h << 3) | (w >> 3);
    __half* op = g_att16 + (size_t)((tok & ~4095) | n2) * 512 + ((w & 7) << 6);

#pragma unroll
    for (int d0 = 0; d0 < 64; d0 += 4) {
        float4 o4 = {0.f, 0.f, 0.f, 0.f};
#pragma unroll
        for (int g = 0; g < 8; g++) {
            const float* vr = &kv[lt][512 + g * 64 + d0];
            o4.x += S[g] * vr[0];
            o4.y += S[g] * vr[1];
            o4.z += S[g] * vr[2];
            o4.w += S[g] * vr[3];
        }
        __half2 h0 = __floats2half2_rn(o4.x, o4.y);
        __half2 h1 = __floats2half2_rn(o4.z, o4.w);
        uint2 u;
        u.x = *(const unsigned*)&h0;
        u.y = *(const unsigned*)&h1;
        *(uint2*)(op + d0) = u;
    }
}

// ---------------------------------------------------------------------------
extern "C" void kernel_launch(void* const* d_in, const int* in_sizes, int n_in,
                              void* d_out, int out_size)
{
    const float* x = (const float*)d_in[0];
    const float* w_qkv = (const float*)d_in[1];
    const float* w_proj = (const float*)d_in[2];
    const float* b_proj = (const float*)d_in[3];
    float* out = (float*)d_out;
    (void)in_sizes; (void)n_in; (void)out_size;

    __half* wq16;
    __half* wp16;
    __half* x16;
    __half* a16;
    cudaGetSymbolAddress((void**)&wq16, g_wqkv16);
    cudaGetSymbolAddress((void**)&wp16, g_wproj16);
    cudaGetSymbolAddress((void**)&x16, g_x16);
    cudaGetSymbolAddress((void**)&a16, g_att16);

    // 1) fp16 conversions (roll(-32) fused into x)
    conv_x_kernel<<<(NTOK * 512 / 4) / 256, 256>>>(x);
    conv_w_kernel<<<(1536 * 512 / 4 + 255) / 256, 256>>>(w_qkv, wq16, 1536 * 512 / 4);
    conv_w_kernel<<<(512 * 512 / 4 + 255) / 256, 256>>>(w_proj, wp16, 512 * 512 / 4);

    // 2) QKV GEMM (tensor cores, cp.async pipelined) -> g_qkv16 fp16
    gemm_wmma<0><<<dim3(1536 / 128, NTOK / 128), 256>>>(x16, wq16, nullptr, nullptr);

    // 3) per-token 8x8 head attention + scramble -> g_att16
    attn_kernel<<<NTOK / 8, 64>>>();

    // 4) proj GEMM + bias + roll(+32) -> d_out
    gemm_wmma<1><<<dim3(512 / 128, NTOK / 128), 256>>>(a16, wp16, b_proj, out);
}